// round 2
// baseline (speedup 1.0000x reference)
#include <cuda_runtime.h>
#include <math.h>

#define DIM 16777216
#define NVEC (DIM / 4)          // 4,194,304 float4 elements
#define THREADS 256
#define BLOCKS (NVEC / THREADS) // 16384

__device__ float g_sum_dev2;
__device__ float g_sum_css2;

__global__ void ni_zero_kernel() {
    g_sum_dev2 = 0.0f;
    g_sum_css2 = 0.0f;
}

__global__ void __launch_bounds__(THREADS) ni_main_kernel(
    const float* __restrict__ css_in,   // (4, DIM)
    const float* __restrict__ narr,     // (DIM,)
    const float* __restrict__ tonic,    // (DIM,)
    float* __restrict__ out)            // out[0:DIM)=new_narrative, [DIM:2DIM)=velocity
{
    const int i = blockIdx.x * blockDim.x + threadIdx.x;  // float4 index

    const float4* a0 = reinterpret_cast<const float4*>(css_in);
    const float4* a1 = a0 + NVEC;
    const float4* a2 = a1 + NVEC;
    const float4* a3 = a2 + NVEC;
    const float4* n4 = reinterpret_cast<const float4*>(narr);
    const float4* t4 = reinterpret_cast<const float4*>(tonic);
    float4* out_nn  = reinterpret_cast<float4*>(out);
    float4* out_vel = out_nn + NVEC;

    float4 v0 = a0[i];
    float4 v1 = a1[i];
    float4 v2 = a2[i];
    float4 v3 = a3[i];
    float4 n  = n4[i];
    float4 t  = t4[i];

    float dev2 = 0.0f;
    float c2   = 0.0f;
    float4 nn, vel;

    {
        float css = (v0.x + v1.x + v2.x + v3.x) * 0.25f;
        float d   = css - n.x;
        dev2 += d * d;  c2 += css * css;
        nn.x  = n.x * 0.99f + css * 0.01f + t.x;
        vel.x = nn.x - n.x;
    }
    {
        float css = (v0.y + v1.y + v2.y + v3.y) * 0.25f;
        float d   = css - n.y;
        dev2 += d * d;  c2 += css * css;
        nn.y  = n.y * 0.99f + css * 0.01f + t.y;
        vel.y = nn.y - n.y;
    }
    {
        float css = (v0.z + v1.z + v2.z + v3.z) * 0.25f;
        float d   = css - n.z;
        dev2 += d * d;  c2 += css * css;
        nn.z  = n.z * 0.99f + css * 0.01f + t.z;
        vel.z = nn.z - n.z;
    }
    {
        float css = (v0.w + v1.w + v2.w + v3.w) * 0.25f;
        float d   = css - n.w;
        dev2 += d * d;  c2 += css * css;
        nn.w  = n.w * 0.99f + css * 0.01f + t.w;
        vel.w = nn.w - n.w;
    }

    out_nn[i]  = nn;
    out_vel[i] = vel;

    // Warp reduce both sums
    #pragma unroll
    for (int off = 16; off > 0; off >>= 1) {
        dev2 += __shfl_down_sync(0xFFFFFFFFu, dev2, off);
        c2   += __shfl_down_sync(0xFFFFFFFFu, c2,   off);
    }

    __shared__ float s_dev[THREADS / 32];
    __shared__ float s_css[THREADS / 32];
    const int lane = threadIdx.x & 31;
    const int wid  = threadIdx.x >> 5;
    if (lane == 0) { s_dev[wid] = dev2; s_css[wid] = c2; }
    __syncthreads();

    if (wid == 0) {
        dev2 = (lane < THREADS / 32) ? s_dev[lane] : 0.0f;
        c2   = (lane < THREADS / 32) ? s_css[lane] : 0.0f;
        #pragma unroll
        for (int off = 4; off > 0; off >>= 1) {
            dev2 += __shfl_down_sync(0xFFFFFFFFu, dev2, off);
            c2   += __shfl_down_sync(0xFFFFFFFFu, c2,   off);
        }
        if (lane == 0) {
            atomicAdd(&g_sum_dev2, dev2);
            atomicAdd(&g_sum_css2, c2);
        }
    }
}

__global__ void ni_epilogue_kernel(const float* __restrict__ fast_p,
                                   const float* __restrict__ slow_p,
                                   float* __restrict__ out)
{
    const float dev_norm = sqrtf(g_sum_dev2);
    const float css_norm = sqrtf(g_sum_css2);
    const float fast = fast_p[0];
    const float slow = slow_p[0];

    const float consistency_loss = 0.1f * dev_norm;

    const float input_gate = fminf(1.0f, css_norm);
    const float delta_fast = 0.01f / (1.0f + fast * 5.0f) * input_gate;
    const float fast_new   = fminf(fast * 0.9995f + delta_fast, 0.7f);

    const float schema_fit = fminf(fmaxf(1.0f - dev_norm, 0.0f), 1.0f);
    const float schema_mult = 1.0f + 15.0f * schema_fit * schema_fit;
    const float delta_slow = 0.001f / (1.0f + slow * 5.0f) * schema_mult;
    const float slow_new   = fminf(slow + delta_slow, 1.0f);

    const float identity_strength = fminf(fast_new + slow_new, 1.0f);

    out[2 * DIM + 0] = consistency_loss;
    out[2 * DIM + 1] = identity_strength;
    out[2 * DIM + 2] = dev_norm;
}

extern "C" void kernel_launch(void* const* d_in, const int* in_sizes, int n_in,
                              void* d_out, int out_size)
{
    const float* css   = (const float*)d_in[0];  // (4, DIM)
    const float* narr  = (const float*)d_in[1];  // (DIM,)
    const float* tonic = (const float*)d_in[2];  // (DIM,)
    const float* fast  = (const float*)d_in[3];  // scalar
    const float* slow  = (const float*)d_in[4];  // scalar
    float* out = (float*)d_out;

    ni_zero_kernel<<<1, 1>>>();
    ni_main_kernel<<<BLOCKS, THREADS>>>(css, narr, tonic, out);
    ni_epilogue_kernel<<<1, 1>>>(fast, slow, out);
}

// round 3
// speedup vs baseline: 1.0004x; 1.0004x over previous
#include <cuda_runtime.h>
#include <math.h>

#define DIM 16777216
#define NVEC (DIM / 4)          // 4,194,304 float4 elements
#define THREADS 256
#define BLOCKS (NVEC / THREADS) // 16384

__device__ float g_sum_dev2;
__device__ float g_sum_css2;

__global__ void ni_zero_kernel() {
    g_sum_dev2 = 0.0f;
    g_sum_css2 = 0.0f;
}

__global__ void __launch_bounds__(THREADS) ni_main_kernel(
    const float* __restrict__ css_in,   // (4, DIM)
    const float* __restrict__ narr,     // (DIM,)
    const float* __restrict__ tonic,    // (DIM,)
    float* __restrict__ out)            // out[0:DIM)=new_narrative, [DIM:2DIM)=velocity
{
    const int i = blockIdx.x * blockDim.x + threadIdx.x;  // float4 index

    const float4* a0 = reinterpret_cast<const float4*>(css_in);
    const float4* a1 = a0 + NVEC;
    const float4* a2 = a1 + NVEC;
    const float4* a3 = a2 + NVEC;
    const float4* n4 = reinterpret_cast<const float4*>(narr);
    const float4* t4 = reinterpret_cast<const float4*>(tonic);
    float4* out_nn  = reinterpret_cast<float4*>(out);
    float4* out_vel = out_nn + NVEC;

    float4 v0 = a0[i];
    float4 v1 = a1[i];
    float4 v2 = a2[i];
    float4 v3 = a3[i];
    float4 n  = n4[i];
    float4 t  = t4[i];

    float dev2 = 0.0f;
    float c2   = 0.0f;
    float4 nn, vel;

    {
        float css = (v0.x + v1.x + v2.x + v3.x) * 0.25f;
        float d   = css - n.x;
        dev2 += d * d;  c2 += css * css;
        nn.x  = n.x * 0.99f + css * 0.01f + t.x;
        vel.x = nn.x - n.x;
    }
    {
        float css = (v0.y + v1.y + v2.y + v3.y) * 0.25f;
        float d   = css - n.y;
        dev2 += d * d;  c2 += css * css;
        nn.y  = n.y * 0.99f + css * 0.01f + t.y;
        vel.y = nn.y - n.y;
    }
    {
        float css = (v0.z + v1.z + v2.z + v3.z) * 0.25f;
        float d   = css - n.z;
        dev2 += d * d;  c2 += css * css;
        nn.z  = n.z * 0.99f + css * 0.01f + t.z;
        vel.z = nn.z - n.z;
    }
    {
        float css = (v0.w + v1.w + v2.w + v3.w) * 0.25f;
        float d   = css - n.w;
        dev2 += d * d;  c2 += css * css;
        nn.w  = n.w * 0.99f + css * 0.01f + t.w;
        vel.w = nn.w - n.w;
    }

    out_nn[i]  = nn;
    out_vel[i] = vel;

    // Warp reduce both sums
    #pragma unroll
    for (int off = 16; off > 0; off >>= 1) {
        dev2 += __shfl_down_sync(0xFFFFFFFFu, dev2, off);
        c2   += __shfl_down_sync(0xFFFFFFFFu, c2,   off);
    }

    __shared__ float s_dev[THREADS / 32];
    __shared__ float s_css[THREADS / 32];
    const int lane = threadIdx.x & 31;
    const int wid  = threadIdx.x >> 5;
    if (lane == 0) { s_dev[wid] = dev2; s_css[wid] = c2; }
    __syncthreads();

    if (wid == 0) {
        dev2 = (lane < THREADS / 32) ? s_dev[lane] : 0.0f;
        c2   = (lane < THREADS / 32) ? s_css[lane] : 0.0f;
        #pragma unroll
        for (int off = 4; off > 0; off >>= 1) {
            dev2 += __shfl_down_sync(0xFFFFFFFFu, dev2, off);
            c2   += __shfl_down_sync(0xFFFFFFFFu, c2,   off);
        }
        if (lane == 0) {
            atomicAdd(&g_sum_dev2, dev2);
            atomicAdd(&g_sum_css2, c2);
        }
    }
}

__global__ void ni_epilogue_kernel(const float* __restrict__ fast_p,
                                   const float* __restrict__ slow_p,
                                   float* __restrict__ out)
{
    const float dev_norm = sqrtf(g_sum_dev2);
    const float css_norm = sqrtf(g_sum_css2);
    const float fast = fast_p[0];
    const float slow = slow_p[0];

    const float consistency_loss = 0.1f * dev_norm;

    const float input_gate = fminf(1.0f, css_norm);
    const float delta_fast = 0.01f / (1.0f + fast * 5.0f) * input_gate;
    const float fast_new   = fminf(fast * 0.9995f + delta_fast, 0.7f);

    const float schema_fit = fminf(fmaxf(1.0f - dev_norm, 0.0f), 1.0f);
    const float schema_mult = 1.0f + 15.0f * schema_fit * schema_fit;
    const float delta_slow = 0.001f / (1.0f + slow * 5.0f) * schema_mult;
    const float slow_new   = fminf(slow + delta_slow, 1.0f);

    const float identity_strength = fminf(fast_new + slow_new, 1.0f);

    out[2 * DIM + 0] = consistency_loss;
    out[2 * DIM + 1] = identity_strength;
    out[2 * DIM + 2] = dev_norm;
}

extern "C" void kernel_launch(void* const* d_in, const int* in_sizes, int n_in,
                              void* d_out, int out_size)
{
    const float* css   = (const float*)d_in[0];  // (4, DIM)
    const float* narr  = (const float*)d_in[1];  // (DIM,)
    const float* tonic = (const float*)d_in[2];  // (DIM,)
    const float* fast  = (const float*)d_in[3];  // scalar
    const float* slow  = (const float*)d_in[4];  // scalar
    float* out = (float*)d_out;

    ni_zero_kernel<<<1, 1>>>();
    ni_main_kernel<<<BLOCKS, THREADS>>>(css, narr, tonic, out);
    ni_epilogue_kernel<<<1, 1>>>(fast, slow, out);
}